// round 12
// baseline (speedup 1.0000x reference)
#include <cuda_runtime.h>
#include <cstdint>

#define NB      160            // 5*32 boxes per batch
#define NT      256
#define RSPLIT  16
#define ROWS    32             // rows per CTA
#define MW      17             // padded mask row stride -> conflict-free
#define NCTAS   (64 * RSPLIT)
#define NSTAGE  16             // 16 stages x 2 rows (4KB) = 32-row tile
#define NBUF    4              // ring buffers in flight
#define STGB    4096           // bytes per stage

__device__ float    g_part[64][RSPLIT][4];  // [tanh_sum, painted_tanh_sum, count]
__device__ unsigned g_count = 0;            // self-resetting last-CTA counter

__device__ __forceinline__ float htanh(float x) {
    float t;
    asm("tanh.approx.f32 %0, %1;" : "=f"(t) : "f"(x));
    return t;
}

__device__ __forceinline__ uint32_t s2u(const void* p) {
    uint32_t a;
    asm("{ .reg .u64 t; cvta.to.shared.u64 t, %1; cvt.u32.u64 %0, t; }"
        : "=r"(a) : "l"(p));
    return a;
}

__device__ __forceinline__ void mbar_init(uint32_t a, uint32_t cnt) {
    asm volatile("mbarrier.init.shared.b64 [%0], %1;" :: "r"(a), "r"(cnt) : "memory");
}
__device__ __forceinline__ void mbar_arrive(uint32_t a) {
    asm volatile("mbarrier.arrive.shared.b64 _, [%0];" :: "r"(a) : "memory");
}
__device__ __forceinline__ void mbar_expect_tx(uint32_t a, uint32_t bytes) {
    asm volatile("mbarrier.arrive.expect_tx.shared.b64 _, [%0], %1;"
                 :: "r"(a), "r"(bytes) : "memory");
}
__device__ __forceinline__ void mbar_wait(uint32_t a, uint32_t parity) {
    asm volatile(
        "{\n\t.reg .pred P;\n"
        "W%=:\n\t"
        "mbarrier.try_wait.parity.acquire.cta.shared::cta.b64 P, [%0], %1, 0x989680;\n\t"
        "@P bra D%=;\n\t"
        "bra W%=;\n"
        "D%=:\n\t}"
        :: "r"(a), "r"(parity) : "memory");
}
__device__ __forceinline__ void tma_1d(uint32_t dst, const void* src,
                                       uint32_t bytes, uint32_t mbar) {
    asm volatile(
        "cp.async.bulk.shared::cluster.global.mbarrier::complete_tx::bytes "
        "[%0], [%1], %2, [%3];"
        :: "r"(dst), "l"(src), "r"(bytes), "r"(mbar) : "memory");
}

__global__ void __launch_bounds__(NT, 7)
mml_fused(const float* __restrict__ pred, const int* __restrict__ tgt,
          float* __restrict__ out)
{
    const int b    = blockIdx.x;
    const int seg  = blockIdx.y;
    const int row0 = seg * ROWS;
    const int tid  = threadIdx.x;
    const int lane = tid & 31;
    const int warp = tid >> 5;

    __shared__ __align__(128) float4 stg[NBUF][STGB / 16];  // 16 KB ring
    __shared__ __align__(8) unsigned long long mb_full[NBUF], mb_empty[NBUF];
    __shared__ int4     cbox[NB];
    __shared__ int      s_nbox;
    __shared__ unsigned sm[ROWS * MW];
    __shared__ float    red[3][NT / 32];
    __shared__ float    shl[64];
    __shared__ bool     isLast;

    // box load overlaps mask zeroing + mbarrier init
    const int4* tb = (const int4*)(tgt + (size_t)b * NB * 4);
    int4 mybox;
    if (tid < NB) mybox = tb[tid];

    if (tid == 0) {
        s_nbox = 0;
        #pragma unroll
        for (int i = 0; i < NBUF; i++) {
            mbar_init(s2u(&mb_full[i]), 1);
            mbar_init(s2u(&mb_empty[i]), NT);
        }
    }
    for (int i = tid; i < ROWS * MW; i += NT) sm[i] = 0u;
    __syncthreads();

    // ---- producer: launch the first NBUF stages immediately ----
    const char* gsrc = (const char*)(pred + ((size_t)b * 512 + row0) * 512);
    if (tid == 0) {
        #pragma unroll
        for (int s = 0; s < NBUF; s++) {
            uint32_t fb = s2u(&mb_full[s]);
            mbar_expect_tx(fb, STGB);
            tma_1d(s2u(&stg[s][0]), gsrc + (size_t)s * STGB, STGB, fb);
        }
    }

    // ---- compact boxes intersecting this 32-row segment (overlaps TMA) ----
    if (tid < NB) {
        int x1 = min(mybox.x, 512),           y1 = min(mybox.y, 512);
        int x2 = min(mybox.x + mybox.z, 512), y2 = min(mybox.y + mybox.w, 512);
        if (x2 > row0 && x1 < row0 + ROWS && y2 > y1) {
            int slot = atomicAdd(&s_nbox, 1);
            cbox[slot] = make_int4(max(x1 - row0, 0), min(x2 - row0, ROWS), y1, y2);
        }
    }
    __syncthreads();
    const int nbox = s_nbox;

    // ---- warp-per-box paint: lane = row, padded stride -> 32 distinct banks ----
    for (int i = warp; i < nbox; i += NT / 32) {
        int4 bx = cbox[i];
        int wlo = bx.z >> 5, whi = (bx.w - 1) >> 5;
        unsigned loMask = ~((1u << (bx.z & 31)) - 1u);
        unsigned hiMask = 0xFFFFFFFFu >> (31 - ((bx.w - 1) & 31));
        int r = bx.x + lane;
        if (r < bx.y) {
            unsigned* mrow = &sm[r * MW];
            for (int w = wlo; w <= whi; w++) {
                unsigned bits = 0xFFFFFFFFu;
                if (w == wlo) bits &= loMask;
                if (w == whi) bits &= hiMask;
                atomicOr(&mrow[w], bits);
            }
        }
    }
    __syncthreads();

    // ---- exact painted count: thread owns cells tid and tid+256 ----
    float cntf;
    {
        int c0 = tid, c1 = tid + NT;
        cntf = (float)(__popc(sm[(c0 >> 4) * MW + (c0 & 15)]) +
                       __popc(sm[(c1 >> 4) * MW + (c1 & 15)]));
    }

    // ---- prepack 16 mask nibbles (nibble k == pipeline stage k) ----
    const int c4   = tid & 127;
    const int wofs = c4 >> 3;
    const int msh  = (c4 & 7) * 4;
    const int rb   = tid >> 7;                 // 0 or 1
    unsigned mlo = 0u, mhi = 0u;
    #pragma unroll
    for (int k = 0; k < 8; k++) {
        mlo |= ((sm[(rb + 2 * k) * MW + wofs] >> msh) & 0xFu) << (4 * k);
        mhi |= ((sm[(rb + 2 * (k + 8)) * MW + wofs] >> msh) & 0xFu) << (4 * k);
    }

    // ---- TMA-fed pipeline: stage s = rows {2s+rb}; thread reads stg[s%4][tid] ----
    float tsum = 0.f, tisum = 0.f;
    #pragma unroll
    for (int s = 0; s < NSTAGE; s++) {
        const int bf = s & 3;
        const uint32_t par = (s >> 2) & 1;
        mbar_wait(s2u(&mb_full[bf]), par);

        float4 v = stg[bf][tid];
        float t0 = htanh(0.5f * v.x), t1 = htanh(0.5f * v.y);
        float t2 = htanh(0.5f * v.z), t3 = htanh(0.5f * v.w);
        tsum += (t0 + t1) + (t2 + t3);
        unsigned mw = ((s < 8) ? (mlo >> (4 * s)) : (mhi >> (4 * (s - 8)))) & 0xFu;
        if (mw & 1u) tisum += t0;
        if (mw & 2u) tisum += t1;
        if (mw & 4u) tisum += t2;
        if (mw & 8u) tisum += t3;

        if (s < NSTAGE - NBUF) {               // buffer gets reused for stage s+4
            mbar_arrive(s2u(&mb_empty[bf]));
            if (tid == 0) {
                mbar_wait(s2u(&mb_empty[bf]), par);
                uint32_t fb = s2u(&mb_full[bf]);
                mbar_expect_tx(fb, STGB);
                tma_1d(s2u(&stg[bf][0]), gsrc + (size_t)(s + NBUF) * STGB, STGB, fb);
            }
        }
    }

    // ---- block reduce ----
    #pragma unroll
    for (int off = 16; off; off >>= 1) {
        tsum  += __shfl_down_sync(0xffffffffu, tsum,  off);
        tisum += __shfl_down_sync(0xffffffffu, tisum, off);
        cntf  += __shfl_down_sync(0xffffffffu, cntf,  off);
    }
    if (lane == 0) { red[0][warp] = tsum; red[1][warp] = tisum; red[2][warp] = cntf; }
    __syncthreads();
    if (tid == 0) {
        float T = 0.f, TI = 0.f, C = 0.f;
        #pragma unroll
        for (int w = 0; w < NT / 32; w++) { T += red[0][w]; TI += red[1][w]; C += red[2][w]; }
        g_part[b][seg][0] = T;
        g_part[b][seg][1] = TI;
        g_part[b][seg][2] = C;
        __threadfence();
        unsigned prev = atomicAdd(&g_count, 1u);
        isLast = (prev == NCTAS - 1);
        if (isLast) g_count = 0;               // self-reset for graph replay
    }
    __syncthreads();

    // ---- fused final dice reduction in last CTA ----
    if (isLast) {
        __threadfence();
        if (tid < 64) {
            volatile float* gp = (volatile float*)g_part;
            float T = 0.f, TI = 0.f, C = 0.f;
            for (int s = 0; s < RSPLIT; s++) {
                T  += gp[(tid * RSPLIT + s) * 4 + 0];
                TI += gp[(tid * RSPLIT + s) * 4 + 1];
                C  += gp[(tid * RSPLIT + s) * 4 + 2];
            }
            // unfold: P = 0.5*T + 0.5*512*512 ; I = 0.5*TI + 0.5*C
            float P = 0.5f * T + 131072.0f;
            float I = 0.5f * TI + 0.5f * C;
            float inter = 255.f * I;
            shl[tid] = (inter + 1.f) / (P + 255.f * C - inter + 1.f);
        }
        __syncthreads();
        #pragma unroll
        for (int off = 32; off; off >>= 1) {
            if (tid < off && tid + off < 64) shl[tid] += shl[tid + off];
            __syncthreads();
        }
        if (tid == 0) out[0] = 1.0f - shl[0] * (1.0f / 64.0f);
    }
}

extern "C" void kernel_launch(void* const* d_in, const int* in_sizes, int n_in,
                              void* d_out, int out_size) {
    const float* pred = (const float*)d_in[0];   // (64,1,512,512) fp32
    const int*   tgt  = (const int*)d_in[1];     // (64,5,32,4) int32
    float* out = (float*)d_out;                  // scalar

    mml_fused<<<dim3(64, RSPLIT), NT>>>(pred, tgt, out);
}

// round 13
// speedup vs baseline: 1.1704x; 1.1704x over previous
#include <cuda_runtime.h>
#include <cstdint>

#define NB      160            // 5*32 boxes per batch
#define NT      256
#define RSPLIT  16
#define ROWS    32             // rows per CTA
#define MW      17             // padded mask row stride (words) -> conflict-free
#define NCTAS   (64 * RSPLIT)

__device__ float    g_part[64][RSPLIT][4];  // [tanh_sum, painted_tanh_sum, count]
__device__ unsigned g_count = 0;            // self-resetting last-CTA counter

// hardware tanh: 1 MUFU op
__device__ __forceinline__ float htanh(float x) {
    float t;
    asm("tanh.approx.f32 %0, %1;" : "=f"(t) : "f"(x));
    return t;
}

// float4 load with L2 evict_last policy: keeps pred resident in the 126MB L2
// across graph replays (67MB working set fits).
__device__ __forceinline__ float4 ld4_keep(const float4* p, uint64_t pol) {
    float4 v;
    asm volatile("ld.global.L2::cache_hint.v4.f32 {%0,%1,%2,%3}, [%4], %5;"
                 : "=f"(v.x), "=f"(v.y), "=f"(v.z), "=f"(v.w)
                 : "l"(p), "l"(pol));
    return v;
}

__global__ void __launch_bounds__(NT, 7)
mml_fused(const float* __restrict__ pred, const int* __restrict__ tgt,
          float* __restrict__ out)
{
    const int b    = blockIdx.x;
    const int seg  = blockIdx.y;
    const int row0 = seg * ROWS;
    const int tid  = threadIdx.x;
    const int lane = tid & 31;
    const int warp = tid >> 5;

    __shared__ int4     cbox[NB];          // compacted: (r0loc, r1loc, y1, y2)
    __shared__ int      s_nbox;
    __shared__ unsigned sm[ROWS * MW];     // padded mask tile
    __shared__ float    red[3][NT / 32];
    __shared__ float    shl[64];
    __shared__ bool     isLast;

    // L2 evict_last policy (whole line class)
    uint64_t pol;
    asm("createpolicy.fractional.L2::evict_last.b64 %0, 1.0;" : "=l"(pol));

    // box load overlaps smem zeroing
    const int4* tb = (const int4*)(tgt + (size_t)b * NB * 4);
    int4 mybox;
    if (tid < NB) mybox = tb[tid];

    if (tid == 0) s_nbox = 0;
    for (int i = tid; i < ROWS * MW; i += NT) sm[i] = 0u;
    __syncthreads();

    // ---- compact boxes intersecting this 32-row segment ----
    if (tid < NB) {
        int x1 = min(mybox.x, 512),           y1 = min(mybox.y, 512);
        int x2 = min(mybox.x + mybox.z, 512), y2 = min(mybox.y + mybox.w, 512);
        if (x2 > row0 && x1 < row0 + ROWS && y2 > y1) {
            int slot = atomicAdd(&s_nbox, 1);
            cbox[slot] = make_int4(max(x1 - row0, 0), min(x2 - row0, ROWS), y1, y2);
        }
    }
    __syncthreads();
    const int nbox = s_nbox;

    // ---- warp-per-box paint: lane = row, padded stride -> 32 distinct banks ----
    for (int i = warp; i < nbox; i += NT / 32) {
        int4 bx = cbox[i];
        int wlo = bx.z >> 5, whi = (bx.w - 1) >> 5;
        unsigned loMask = ~((1u << (bx.z & 31)) - 1u);
        unsigned hiMask = 0xFFFFFFFFu >> (31 - ((bx.w - 1) & 31));
        int r = bx.x + lane;
        if (r < bx.y) {
            unsigned* mrow = &sm[r * MW];
            for (int w = wlo; w <= whi; w++) {
                unsigned bits = 0xFFFFFFFFu;
                if (w == wlo) bits &= loMask;
                if (w == whi) bits &= hiMask;
                atomicOr(&mrow[w], bits);
            }
        }
    }
    __syncthreads();

    // ---- exact painted count: thread owns cells tid and tid+256 ----
    float cntf;
    {
        int c0 = tid, c1 = tid + NT;
        cntf = (float)(__popc(sm[(c0 >> 4) * MW + (c0 & 15)]) +
                       __popc(sm[(c1 >> 4) * MW + (c1 & 15)]));
    }

    // ---- prepack this thread's 16 mask nibbles into two u32 regs ----
    const int c4   = tid & 127;
    const int wofs = c4 >> 3;
    const int msh  = (c4 & 7) * 4;
    const int rb   = tid >> 7;                 // 0 or 1
    unsigned mlo = 0u, mhi = 0u;
    #pragma unroll
    for (int k = 0; k < 8; k++) {
        mlo |= ((sm[(rb + 2 * k) * MW + wofs] >> msh) & 0xFu) << (4 * k);
        mhi |= ((sm[(rb + 2 * (k + 8)) * MW + wofs] >> msh) & 0xFu) << (4 * k);
    }

    // ---- streaming loop: sigmoid = 0.5*tanh(x/2)+0.5; constants folded out ----
    float tsum = 0.f, tisum = 0.f;
    const float4* p = (const float4*)(pred + ((size_t)b * 512 + row0) * 512);
    #pragma unroll 4
    for (int k = 0; k < ROWS * 512 / 4 / NT; k++) {
        float4 v = ld4_keep(p + tid + NT * k, pol);
        float t0 = htanh(0.5f * v.x), t1 = htanh(0.5f * v.y);
        float t2 = htanh(0.5f * v.z), t3 = htanh(0.5f * v.w);
        tsum += (t0 + t1) + (t2 + t3);
        unsigned mw = ((k < 8 ? mlo : mhi) >> (4 * (k & 7))) & 0xFu;
        if (mw & 1u) tisum += t0;
        if (mw & 2u) tisum += t1;
        if (mw & 4u) tisum += t2;
        if (mw & 8u) tisum += t3;
    }

    // ---- block reduce ----
    #pragma unroll
    for (int off = 16; off; off >>= 1) {
        tsum  += __shfl_down_sync(0xffffffffu, tsum,  off);
        tisum += __shfl_down_sync(0xffffffffu, tisum, off);
        cntf  += __shfl_down_sync(0xffffffffu, cntf,  off);
    }
    if (lane == 0) { red[0][warp] = tsum; red[1][warp] = tisum; red[2][warp] = cntf; }
    __syncthreads();
    if (tid == 0) {
        float T = 0.f, TI = 0.f, C = 0.f;
        #pragma unroll
        for (int w = 0; w < NT / 32; w++) { T += red[0][w]; TI += red[1][w]; C += red[2][w]; }
        g_part[b][seg][0] = T;
        g_part[b][seg][1] = TI;
        g_part[b][seg][2] = C;
        __threadfence();
        unsigned prev = atomicAdd(&g_count, 1u);
        isLast = (prev == NCTAS - 1);
        if (isLast) g_count = 0;               // self-reset for graph replay
    }
    __syncthreads();

    // ---- fused final dice reduction in last CTA ----
    if (isLast) {
        __threadfence();
        if (tid < 64) {
            volatile float* gp = (volatile float*)g_part;
            float T = 0.f, TI = 0.f, C = 0.f;
            for (int s = 0; s < RSPLIT; s++) {
                T  += gp[(tid * RSPLIT + s) * 4 + 0];
                TI += gp[(tid * RSPLIT + s) * 4 + 1];
                C  += gp[(tid * RSPLIT + s) * 4 + 2];
            }
            // unfold: P = 0.5*T + 0.5*512*512 ; I = 0.5*TI + 0.5*C
            float P = 0.5f * T + 131072.0f;
            float I = 0.5f * TI + 0.5f * C;
            float inter = 255.f * I;
            shl[tid] = (inter + 1.f) / (P + 255.f * C - inter + 1.f);
        }
        __syncthreads();
        #pragma unroll
        for (int off = 32; off; off >>= 1) {
            if (tid < off && tid + off < 64) shl[tid] += shl[tid + off];
            __syncthreads();
        }
        if (tid == 0) out[0] = 1.0f - shl[0] * (1.0f / 64.0f);
    }
}

extern "C" void kernel_launch(void* const* d_in, const int* in_sizes, int n_in,
                              void* d_out, int out_size) {
    const float* pred = (const float*)d_in[0];   // (64,1,512,512) fp32
    const int*   tgt  = (const int*)d_in[1];     // (64,5,32,4) int32
    float* out = (float*)d_out;                  // scalar

    mml_fused<<<dim3(64, RSPLIT), NT>>>(pred, tgt, out);
}

// round 15
// speedup vs baseline: 1.2277x; 1.0489x over previous
#include <cuda_runtime.h>
#include <cstdint>

#define NB      160            // 5*32 boxes per batch
#define NT      256
#define RSPLIT  16
#define ROWS    32             // rows per CTA
#define MW      17             // padded mask row stride (words) -> conflict-free
#define NCTAS   (64 * RSPLIT)

__device__ float    g_part[64][RSPLIT][4];  // [tanh_sum, painted_tanh_sum, count]
__device__ unsigned g_count = 0;            // self-resetting last-CTA counter

// hardware tanh: 1 MUFU op
__device__ __forceinline__ float htanh(float x) {
    float t;
    asm("tanh.approx.f32 %0, %1;" : "=f"(t) : "f"(x));
    return t;
}

__global__ void __launch_bounds__(NT, 6)
mml_fused(const float* __restrict__ pred, const int* __restrict__ tgt,
          float* __restrict__ out)
{
    const int b    = blockIdx.x;
    const int seg  = blockIdx.y;
    const int row0 = seg * ROWS;
    const int tid  = threadIdx.x;
    const int lane = tid & 31;
    const int warp = tid >> 5;

    __shared__ int4     cbox[NB];          // compacted: (r0loc, r1loc, y1, y2)
    __shared__ int      s_nbox;
    __shared__ unsigned sm[ROWS * MW];     // padded mask tile
    __shared__ float    red[3][NT / 32];
    __shared__ float    shl[64];
    __shared__ bool     isLast;

    // box load overlaps smem zeroing
    const int4* tb = (const int4*)(tgt + (size_t)b * NB * 4);
    int4 mybox;
    if (tid < NB) mybox = tb[tid];

    if (tid == 0) s_nbox = 0;
    for (int i = tid; i < ROWS * MW; i += NT) sm[i] = 0u;
    __syncthreads();

    // ---- compact boxes intersecting this 32-row segment ----
    if (tid < NB) {
        int x1 = min(mybox.x, 512),           y1 = min(mybox.y, 512);
        int x2 = min(mybox.x + mybox.z, 512), y2 = min(mybox.y + mybox.w, 512);
        if (x2 > row0 && x1 < row0 + ROWS && y2 > y1) {
            int slot = atomicAdd(&s_nbox, 1);
            cbox[slot] = make_int4(max(x1 - row0, 0), min(x2 - row0, ROWS), y1, y2);
        }
    }
    __syncthreads();
    const int nbox = s_nbox;

    // ---- warp-per-box paint: lane = row, padded stride -> 32 distinct banks ----
    for (int i = warp; i < nbox; i += NT / 32) {
        int4 bx = cbox[i];
        int wlo = bx.z >> 5, whi = (bx.w - 1) >> 5;
        unsigned loMask = ~((1u << (bx.z & 31)) - 1u);
        unsigned hiMask = 0xFFFFFFFFu >> (31 - ((bx.w - 1) & 31));
        int r = bx.x + lane;
        if (r < bx.y) {
            unsigned* mrow = &sm[r * MW];
            for (int w = wlo; w <= whi; w++) {
                unsigned bits = 0xFFFFFFFFu;
                if (w == wlo) bits &= loMask;
                if (w == whi) bits &= hiMask;
                atomicOr(&mrow[w], bits);
            }
        }
    }
    __syncthreads();

    // ---- exact painted count: thread owns cells tid and tid+256 ----
    float cntf;
    {
        int c0 = tid, c1 = tid + NT;
        cntf = (float)(__popc(sm[(c0 >> 4) * MW + (c0 & 15)]) +
                       __popc(sm[(c1 >> 4) * MW + (c1 & 15)]));
    }

    // ---- prepack this thread's 16 mask nibbles into two u32 regs ----
    const int c4   = tid & 127;
    const int wofs = c4 >> 3;
    const int msh  = (c4 & 7) * 4;
    const int rb   = tid >> 7;                 // 0 or 1
    unsigned mlo = 0u, mhi = 0u;
    #pragma unroll
    for (int k = 0; k < 8; k++) {
        mlo |= ((sm[(rb + 2 * k) * MW + wofs] >> msh) & 0xFu) << (4 * k);
        mhi |= ((sm[(rb + 2 * (k + 8)) * MW + wofs] >> msh) & 0xFu) << (4 * k);
    }

    // ---- streaming loop: 4 front-batched LDG.128 per outer iter (MLP_p1 = 4),
    //      then sigmoid = 0.5*tanh(x/2)+0.5 with constants folded out,
    //      masked adds tree-summed to shorten the tisum dependency chain.
    float tsum = 0.f, tisum = 0.f;
    const float4* p = (const float4*)(pred + ((size_t)b * 512 + row0) * 512);

#define PROC(v, mw)                                                        \
    {   float t0 = htanh(0.5f * (v).x), t1 = htanh(0.5f * (v).y);          \
        float t2 = htanh(0.5f * (v).z), t3 = htanh(0.5f * (v).w);          \
        tsum += (t0 + t1) + (t2 + t3);                                     \
        float a0 = ((mw) & 1u) ? t0 : 0.f;                                 \
        float a1 = ((mw) & 2u) ? t1 : 0.f;                                 \
        float a2 = ((mw) & 4u) ? t2 : 0.f;                                 \
        float a3 = ((mw) & 8u) ? t3 : 0.f;                                 \
        tisum += (a0 + a1) + (a2 + a3); }

    #pragma unroll
    for (int g = 0; g < 4; g++) {
        // 4 consecutive LDG.128, no intervening math -> guaranteed batched
        const float4* base = p + tid + NT * 4 * g;
        float4 v0 = base[0];
        float4 v1 = base[NT];
        float4 v2 = base[2 * NT];
        float4 v3 = base[3 * NT];
        const unsigned nib = (g < 2) ? (mlo >> (16 * g)) : (mhi >> (16 * (g - 2)));
        PROC(v0, (nib      ) & 0xFu);
        PROC(v1, (nib >>  4) & 0xFu);
        PROC(v2, (nib >>  8) & 0xFu);
        PROC(v3, (nib >> 12) & 0xFu);
    }
#undef PROC

    // ---- block reduce ----
    #pragma unroll
    for (int off = 16; off; off >>= 1) {
        tsum  += __shfl_down_sync(0xffffffffu, tsum,  off);
        tisum += __shfl_down_sync(0xffffffffu, tisum, off);
        cntf  += __shfl_down_sync(0xffffffffu, cntf,  off);
    }
    if (lane == 0) { red[0][warp] = tsum; red[1][warp] = tisum; red[2][warp] = cntf; }
    __syncthreads();
    if (tid == 0) {
        float T = 0.f, TI = 0.f, C = 0.f;
        #pragma unroll
        for (int w = 0; w < NT / 32; w++) { T += red[0][w]; TI += red[1][w]; C += red[2][w]; }
        g_part[b][seg][0] = T;
        g_part[b][seg][1] = TI;
        g_part[b][seg][2] = C;
        __threadfence();
        unsigned prev = atomicAdd(&g_count, 1u);
        isLast = (prev == NCTAS - 1);
        if (isLast) g_count = 0;               // self-reset for graph replay
    }
    __syncthreads();

    // ---- fused final dice reduction in last CTA ----
    if (isLast) {
        __threadfence();
        if (tid < 64) {
            volatile float* gp = (volatile float*)g_part;
            float T = 0.f, TI = 0.f, C = 0.f;
            for (int s = 0; s < RSPLIT; s++) {
                T  += gp[(tid * RSPLIT + s) * 4 + 0];
                TI += gp[(tid * RSPLIT + s) * 4 + 1];
                C  += gp[(tid * RSPLIT + s) * 4 + 2];
            }
            // unfold: P = 0.5*T + 0.5*512*512 ; I = 0.5*TI + 0.5*C
            float P = 0.5f * T + 131072.0f;
            float I = 0.5f * TI + 0.5f * C;
            float inter = 255.f * I;
            shl[tid] = (inter + 1.f) / (P + 255.f * C - inter + 1.f);
        }
        __syncthreads();
        #pragma unroll
        for (int off = 32; off; off >>= 1) {
            if (tid < off && tid + off < 64) shl[tid] += shl[tid + off];
            __syncthreads();
        }
        if (tid == 0) out[0] = 1.0f - shl[0] * (1.0f / 64.0f);
    }
}

extern "C" void kernel_launch(void* const* d_in, const int* in_sizes, int n_in,
                              void* d_out, int out_size) {
    const float* pred = (const float*)d_in[0];   // (64,1,512,512) fp32
    const int*   tgt  = (const int*)d_in[1];     // (64,5,32,4) int32
    float* out = (float*)d_out;                  // scalar

    mml_fused<<<dim3(64, RSPLIT), NT>>>(pred, tgt, out);
}